// round 15
// baseline (speedup 1.0000x reference)
#include <cuda_runtime.h>
#include <cuda_fp16.h>
#include <cstdint>

#define N_NODES 30000
#define N_EDGES 240000
#define NGRAPH  16
#define D1      256
#define D2      512
#define D3      1024

#define ROWS_H0 14976               // 117 blocks of 128 rows
#define NODE8_H0 (ROWS_H0 / 8)      // 1872 gather blocks for half 0

// ---------------- scratch (no allocations allowed) ----------------
__device__ int   d_idx64;
__device__ int   d_alloc;
__device__ int   d_cin[N_NODES];
__device__ int   d_rowptr[N_NODES];
__device__ int   d_cursor[N_NODES];
__device__ __align__(16) int2 d_epay[N_EDGES];
__device__ float d_dis[N_NODES];
__device__ float d_s1 [N_NODES];
__device__ __align__(16) float d_pool[NGRAPH * D3];
__device__ float d_cnt[NGRAPH];

__device__ __align__(16) __half d_a2h[N_NODES * D1];
__device__ __align__(16) __half d_h2h[N_NODES * D2];
__device__ __align__(16) __half d_a3h[N_NODES * D2];
__device__ __align__(16) __half d_b2h[D2 * D1];   // [N=512, K=256] K-major
__device__ __align__(16) __half d_b3h[D3 * D2];   // [N=1024, K=512] K-major

// ---------------- small helpers ----------------
__device__ __forceinline__ int load_idx(const void* p, int i) {
    if (d_idx64) return (int)((const long long*)p)[i];
    return ((const int*)p)[i];
}
__device__ __forceinline__ void red_add_f32(float* p, float v) {
    asm volatile("red.global.add.f32 [%0], %1;" :: "l"(p), "f"(v) : "memory");
}
__device__ __forceinline__ void red_add_v2(float* p, float x, float y) {
    asm volatile("red.global.add.v2.f32 [%0], {%1,%2};"
                 :: "l"(p), "f"(x), "f"(y) : "memory");
}
__device__ __forceinline__ uint32_t smem_u32(const void* p) {
    uint32_t a;
    asm("{ .reg .u64 t; cvta.to.shared.u64 t, %1; cvt.u32.u64 %0, t; }" : "=r"(a) : "l"(p));
    return a;
}
__device__ __forceinline__ void ldm_x4(uint32_t* r, uint32_t addr) {
    asm volatile("ldmatrix.sync.aligned.m8n8.x4.shared.b16 {%0,%1,%2,%3}, [%4];"
                 : "=r"(r[0]), "=r"(r[1]), "=r"(r[2]), "=r"(r[3]) : "r"(addr));
}
__device__ __forceinline__ void cp_async16(uint32_t dst, const void* src, uint32_t srcsize) {
    asm volatile("cp.async.cg.shared.global [%0], [%1], 16, %2;"
                 :: "r"(dst), "l"(src), "r"(srcsize) : "memory");
}
__device__ __forceinline__ void cp_commit(void) {
    asm volatile("cp.async.commit_group;" ::: "memory");
}
__device__ __forceinline__ void mma16816(float* c, const uint32_t* a, uint32_t b0, uint32_t b1) {
    asm volatile(
        "mma.sync.aligned.m16n8k16.row.col.f32.f16.f16.f32 "
        "{%0,%1,%2,%3}, {%4,%5,%6,%7}, {%8,%9}, {%0,%1,%2,%3};"
        : "+f"(c[0]), "+f"(c[1]), "+f"(c[2]), "+f"(c[3])
        : "r"(a[0]), "r"(a[1]), "r"(a[2]), "r"(a[3]), "r"(b0), "r"(b1));
}
__device__ __forceinline__ float2 h2f2(uint32_t u) {
    __half2 h = *reinterpret_cast<__half2*>(&u);
    return __half22float2(h);
}
__device__ __forceinline__ uint32_t f2h2(float a, float b) {
    __half2 h = __floats2half2_rn(a, b);
    return *reinterpret_cast<uint32_t*>(&h);
}

// ---------------- setup ----------------
__global__ void k_init(const void* __restrict__ ei, const float* __restrict__ bo,
                       float* __restrict__ out) {
    int i = blockIdx.x * blockDim.x + threadIdx.x;
    if (i < N_NODES) d_cin[i] = 0;
    if (i < NGRAPH) d_cnt[i] = 0.0f;
    if (i < NGRAPH * D3) {
        d_pool[i] = 0.0f;
        out[i] = bo[i & (D3 - 1)];
    }
    if (i == 0) {
        d_alloc = 0;
        const long long* p = (const long long*)ei;
        int ok = 1;
        for (int j = 0; j < 64; j++) {
            long long v = p[j];
            if (v < 0 || v >= N_NODES) { ok = 0; break; }
        }
        d_idx64 = ok;
    }
}

// in-degree + batch count, 4 items/thread, warp-aggregated cnt atomics
__global__ void k_deg_cnt(const void* __restrict__ ei, const void* __restrict__ batch) {
    int base = (blockIdx.x * blockDim.x + threadIdx.x) * 4;
    int dst[4];
#pragma unroll
    for (int j = 0; j < 4; j++) {
        int e = base + j;
        dst[j] = (e < N_EDGES) ? load_idx(ei, N_EDGES + e) : -1;
    }
#pragma unroll
    for (int j = 0; j < 4; j++)
        if (dst[j] >= 0) atomicAdd(&d_cin[dst[j]], 1);

    int g0 = -1, c0 = 0, g1 = -1, c1 = 0;
#pragma unroll
    for (int j = 0; j < 4; j++) {
        int i = base + j;
        if (i >= N_NODES) break;
        int g = load_idx(batch, i);
        if (g == g0) c0++;
        else if (g == g1) c1++;
        else if (g0 < 0) { g0 = g; c0 = 1; }
        else if (g1 < 0) { g1 = g; c1 = 1; }
        else atomicAdd(&d_cnt[g], 1.0f);
    }
    unsigned am = __activemask();
    if (g0 >= 0) {
        unsigned m = __match_any_sync(am, g0);
        float sum = (float)c0;
        for (int off = 16; off; off >>= 1) {
            float v = __shfl_down_sync(am, sum, off);
            int src = (threadIdx.x & 31) + off;
            if ((m >> src) & 1) sum += v;
        }
        if ((threadIdx.x & 31) == (__ffs(m) - 1)) atomicAdd(&d_cnt[g0], sum);
    }
    if (g1 >= 0) atomicAdd(&d_cnt[g1], (float)c1);
}

// dis/s1 + CSR segment allocation
__global__ void k_dis_s1(const float* __restrict__ x) {
    int i = blockIdx.x * blockDim.x + threadIdx.x;
    int lane = threadIdx.x & 31;
    int valid = (i < N_NODES);
    int c = valid ? d_cin[i] : 0;
    if (valid) {
        float r = rsqrtf((float)(c + 1));
        d_dis[i] = r;
        d_s1[i]  = r * r * x[i];
    }
    unsigned mask = 0xffffffffu;
    int incl = c;
#pragma unroll
    for (int off = 1; off < 32; off <<= 1) {
        int v = __shfl_up_sync(mask, incl, off);
        if (lane >= off) incl += v;
    }
    int total = __shfl_sync(mask, incl, 31);
    int base = 0;
    if (lane == 31) base = atomicAdd(&d_alloc, total);
    base = __shfl_sync(mask, base, 31);
    if (valid) {
        int start = base + incl - c;
        d_rowptr[i] = start;
        d_cursor[i] = start;
    }
}

// CSR fill + edge contribution to s1, 2 edges/thread (MLP)
__global__ void k_fill(const void* __restrict__ ei, const float* __restrict__ x) {
    int base = (blockIdx.x * blockDim.x + threadIdx.x) * 2;
    int s[2], d[2];
#pragma unroll
    for (int j = 0; j < 2; j++) {
        int e = base + j;
        if (e < N_EDGES) { s[j] = load_idx(ei, e); d[j] = load_idx(ei, N_EDGES + e); }
        else { s[j] = -1; d[j] = 0; }
    }
    float ds[2], dd[2], xs[2];
#pragma unroll
    for (int j = 0; j < 2; j++) {
        if (s[j] >= 0) { ds[j] = d_dis[s[j]]; dd[j] = d_dis[d[j]]; xs[j] = x[s[j]]; }
    }
#pragma unroll
    for (int j = 0; j < 2; j++) {
        if (s[j] < 0) continue;
        float nv = ds[j] * dd[j];
        int pos = atomicAdd(&d_cursor[d[j]], 1);
        d_epay[pos] = make_int2(s[j], __float_as_int(nv));
        atomicAdd(&d_s1[d[j]], nv * xs[j]);
    }
}

// ---------------- layer 1 gather (node_ofs for pipelined halves) ----------------
__global__ __launch_bounds__(256)
void k_gather1(const float* __restrict__ W1, const float* __restrict__ b1, int node_ofs) {
    __shared__ float sW[D1], sB[D1];
    int tid = threadIdx.x;
    if (tid < D1) { sW[tid] = W1[tid]; sB[tid] = b1[tid]; }
    __syncthreads();
    int warp = tid >> 5, lane = tid & 31;
    int node = node_ofs + blockIdx.x * 8 + warp;
    if (node >= N_NODES) return;
    float w[8], b[8];
#pragma unroll
    for (int q = 0; q < 8; q++) { w[q] = sW[lane * 8 + q]; b[q] = sB[lane * 8 + q]; }
    float acc[8];
    float dis = d_dis[node];
    float coef = dis * dis, sv = d_s1[node];
#pragma unroll
    for (int q = 0; q < 8; q++) acc[q] = coef * fmaxf(fmaf(sv, w[q], b[q]), 0.0f);
    int beg = d_rowptr[node], end = beg + d_cin[node];
    for (int e = beg; e < end; e++) {
        int2 pay = d_epay[e];
        float nv = __int_as_float(pay.y);
        float s = d_s1[pay.x];
#pragma unroll
        for (int q = 0; q < 8; q++) acc[q] = fmaf(nv, fmaxf(fmaf(s, w[q], b[q]), 0.0f), acc[q]);
    }
    uint32_t hw[4];
#pragma unroll
    for (int q2 = 0; q2 < 4; q2++) hw[q2] = f2h2(acc[q2 * 2], acc[q2 * 2 + 1]);
    size_t off = (size_t)node * D1 + lane * 8;
    *(uint4*)(d_a2h + off) = make_uint4(hw[0], hw[1], hw[2], hw[3]);
}

// ---------------- layer 2 gather (node_ofs for pipelined halves) ----------------
__device__ __forceinline__ void acc_row16(float* acc, int row, float nv, int lane) {
    size_t off = (size_t)row * D2 + lane * 16;
    uint4 h0 = *(const uint4*)(d_h2h + off);
    uint4 h1 = *(const uint4*)(d_h2h + off + 8);
    const uint32_t hu[8] = {h0.x, h0.y, h0.z, h0.w, h1.x, h1.y, h1.z, h1.w};
#pragma unroll
    for (int q = 0; q < 8; q++) {
        float2 hv = h2f2(hu[q]);
        acc[q * 2 + 0] = fmaf(nv, hv.x, acc[q * 2 + 0]);
        acc[q * 2 + 1] = fmaf(nv, hv.y, acc[q * 2 + 1]);
    }
}

__global__ __launch_bounds__(256)
void k_gather2(int node_ofs) {
    int tid = threadIdx.x;
    int warp = tid >> 5, lane = tid & 31;
    int node = node_ofs + blockIdx.x * 8 + warp;
    if (node >= N_NODES) return;
    float acc[16];
#pragma unroll
    for (int q = 0; q < 16; q++) acc[q] = 0.0f;
    float dis = d_dis[node];
    acc_row16(acc, node, dis * dis, lane);
    int beg = d_rowptr[node], end = beg + d_cin[node];
    for (int e = beg; e < end; e++) {
        int2 pay = d_epay[e];
        acc_row16(acc, pay.x, __int_as_float(pay.y), lane);
    }
    uint32_t hw[8];
#pragma unroll
    for (int q2 = 0; q2 < 8; q2++) hw[q2] = f2h2(acc[q2 * 2], acc[q2 * 2 + 1]);
    size_t off = (size_t)node * D2 + lane * 16;
    *(uint4*)(d_a3h + off)     = make_uint4(hw[0], hw[1], hw[2], hw[3]);
    *(uint4*)(d_a3h + off + 8) = make_uint4(hw[4], hw[5], hw[6], hw[7]);
}

// W [K, N] fp32 -> B [N, K] fp16 transposed, tiled/coalesced
__global__ __launch_bounds__(256)
void k_wconv(const float* __restrict__ W, __half* __restrict__ bh, int K, int N) {
    __shared__ float tile[32][33];
    int n0 = blockIdx.x * 32, k0 = blockIdx.y * 32;
    int tx = threadIdx.x & 31, ty = threadIdx.x >> 5;
#pragma unroll
    for (int j = 0; j < 32; j += 8)
        tile[ty + j][tx] = W[(size_t)(k0 + ty + j) * N + n0 + tx];
    __syncthreads();
#pragma unroll
    for (int j = 0; j < 32; j += 8)
        bh[(size_t)(n0 + ty + j) * K + k0 + tx] = __float2half_rn(tile[tx][ty + j]);
}

// ---------------- fp16 GEMM (row_ofs for pipelined halves) ----------------
__global__ __launch_bounds__(256, 2)
void mma_gemm(const __half* __restrict__ A, const __half* __restrict__ B,
              const float* __restrict__ bias, const void* __restrict__ batch,
              int M, int Nglob, int K, int mode, int row_ofs) {
    extern __shared__ __align__(16) char dynsm[];

    const int tid = threadIdx.x;
    const int wid = tid >> 5, lane = tid & 31;
    const int g = lane >> 2, tig = lane & 3;
    const int warp_m = wid & 3, warp_n = wid >> 2;
    const int row0 = blockIdx.y * 128 + row_ofs, col0 = blockIdx.x * 128;
    const int mr = warp_m * 32, nc = warp_n * 64;

    const int t   = lane >> 3;
    const int thi = t >> 1;
    const int rlo = (t & 1) * 8 + (lane & 7);

    const uint32_t smbase = smem_u32(dynsm);
    const uint32_t stA[3] = { smbase, smbase + 32768u, smbase + 65536u };
    const uint32_t stB[3] = { smbase + 16384u, smbase + 49152u, smbase + 81920u };

    int rA0 = mr + rlo, rA1 = mr + 16 + rlo;
    uint32_t aoff0 = (uint32_t)(rA0 * 128), amask0 = (uint32_t)(rA0 & 7);
    uint32_t aoff1 = (uint32_t)(rA1 * 128), amask1 = (uint32_t)(rA1 & 7);
    uint32_t boff[4], bmask[4];
#pragma unroll
    for (int p = 0; p < 4; p++) {
        int rB = nc + p * 16 + rlo;
        boff[p] = (uint32_t)(rB * 128);
        bmask[p] = (uint32_t)(rB & 7);
    }

    float acc[2][8][4];
#pragma unroll
    for (int mf = 0; mf < 2; mf++)
#pragma unroll
        for (int nf = 0; nf < 8; nf++)
#pragma unroll
            for (int q = 0; q < 4; q++) acc[mf][nf][q] = 0.0f;

    const int nk = K >> 6;

    const int lr = tid >> 1;
    const int lc2 = (tid & 1) * 4;
    auto prefetch = [&](int kc, int s) {
        const int kof = kc << 6;
        int grow = row0 + lr;
        uint32_t asz = (grow < M) ? 16u : 0u;
        const __half* agp = A + (size_t)grow * K + kof + lc2 * 8;
        const __half* bgp = B + (size_t)(col0 + lr) * K + kof + lc2 * 8;
        uint32_t arow = (uint32_t)(lr * 128);
#pragma unroll
        for (int j = 0; j < 4; j++) {
            int ch = lc2 + j;
            uint32_t soff = arow + (uint32_t)(((ch ^ (lr & 7)) << 4));
            cp_async16(stA[s] + soff, agp + j * 8, asz);
            cp_async16(stB[s] + soff, bgp + j * 8, 16u);
        }
        cp_commit();
    };

    prefetch(0, 0);
    if (nk > 1) prefetch(1, 1);
    int sidx = 0;
    for (int kc = 0; kc < nk; kc++) {
        if (kc == nk - 1) {
            asm volatile("cp.async.wait_group 0;" ::: "memory");
        } else {
            asm volatile("cp.async.wait_group 1;" ::: "memory");
        }
        __syncthreads();
        if (kc + 2 < nk) prefetch(kc + 2, (sidx + 2) % 3);
        const int s = sidx;

#pragma unroll
        for (int ks = 0; ks < 4; ks++) {
            const uint32_t kg = (uint32_t)(2 * ks + thi);
            uint32_t a0[4], a1[4];
            ldm_x4(a0, stA[s] + aoff0 + (((kg ^ amask0) << 4)));
            ldm_x4(a1, stA[s] + aoff1 + (((kg ^ amask1) << 4)));
#pragma unroll
            for (int p = 0; p < 4; p++) {
                uint32_t bf[4];
                ldm_x4(bf, stB[s] + boff[p] + (((kg ^ bmask[p]) << 4)));
                mma16816(acc[0][2 * p + 0], a0, bf[0], bf[2]);
                mma16816(acc[0][2 * p + 1], a0, bf[1], bf[3]);
                mma16816(acc[1][2 * p + 0], a1, bf[0], bf[2]);
                mma16816(acc[1][2 * p + 1], a1, bf[1], bf[3]);
            }
        }
        sidx = (sidx + 1) % 3;
    }

    // ---------------- epilogue ----------------
    if (mode == 0) {
#pragma unroll
        for (int mf = 0; mf < 2; mf++) {
#pragma unroll
            for (int half = 0; half < 2; half++) {
                int row = row0 + mr + mf * 16 + g + half * 8;
                if (row >= M) continue;
#pragma unroll
                for (int nf = 0; nf < 8; nf++) {
                    int col = col0 + nc + nf * 8 + tig * 2;
                    float2 bv = *(const float2*)&bias[col];
                    float v0 = fmaxf(acc[mf][nf][half * 2 + 0] + bv.x, 0.0f);
                    float v1 = fmaxf(acc[mf][nf][half * 2 + 1] + bv.y, 0.0f);
                    *(uint32_t*)(d_h2h + (size_t)row * D2 + col) = f2h2(v0, v1);
                }
            }
        }
    } else {
#pragma unroll
        for (int mf = 0; mf < 2; mf++) {
            int ra = row0 + mr + mf * 16 + g;
            int v0ok = (ra < M), v1ok = (ra + 8 < M);
#pragma unroll
            for (int nf = 0; nf < 8; nf++) {
                int col = col0 + nc + nf * 8 + tig * 2;
                float2 bv = *(const float2*)&bias[col];
                acc[mf][nf][0] = v0ok ? fmaxf(acc[mf][nf][0] + bv.x, 0.0f) : 0.0f;
                acc[mf][nf][1] = v0ok ? fmaxf(acc[mf][nf][1] + bv.y, 0.0f) : 0.0f;
                acc[mf][nf][2] = v1ok ? fmaxf(acc[mf][nf][2] + bv.x, 0.0f) : 0.0f;
                acc[mf][nf][3] = v1ok ? fmaxf(acc[mf][nf][3] + bv.y, 0.0f) : 0.0f;
            }
        }
        unsigned mask = 0xffffffffu;
        int rv = row0 + mr + lane;
        int bl = (rv < N_NODES) ? load_idx(batch, rv) : -1;
        int b0 = __shfl_sync(mask, bl, 0);
        bool uni = __all_sync(mask, bl == b0);
        if (uni && b0 >= 0) {
            float s[8][2];
#pragma unroll
            for (int nf = 0; nf < 8; nf++) {
                s[nf][0] = acc[0][nf][0] + acc[0][nf][2] + acc[1][nf][0] + acc[1][nf][2];
                s[nf][1] = acc[0][nf][1] + acc[0][nf][3] + acc[1][nf][1] + acc[1][nf][3];
            }
#pragma unroll
            for (int off = 4; off < 32; off <<= 1)
#pragma unroll
                for (int nf = 0; nf < 8; nf++) {
                    s[nf][0] += __shfl_xor_sync(mask, s[nf][0], off);
                    s[nf][1] += __shfl_xor_sync(mask, s[nf][1], off);
                }
            if (lane < 4) {
#pragma unroll
                for (int nf = 0; nf < 8; nf++) {
                    int col = col0 + nc + nf * 8 + lane * 2;
                    red_add_v2(&d_pool[(size_t)b0 * D3 + col], s[nf][0], s[nf][1]);
                }
            }
        } else {
#pragma unroll
            for (int mf = 0; mf < 2; mf++)
#pragma unroll
                for (int half = 0; half < 2; half++) {
                    int row = row0 + mr + mf * 16 + g + half * 8;
                    if (row >= M) continue;
                    int gb = load_idx(batch, row);
#pragma unroll
                    for (int nf = 0; nf < 8; nf++) {
                        int col = col0 + nc + nf * 8 + tig * 2;
                        red_add_v2(&d_pool[(size_t)gb * D3 + col],
                                   acc[mf][nf][half * 2], acc[mf][nf][half * 2 + 1]);
                    }
                }
        }
    }
}

// ---------------- final linear, K-split + atomics ----------------
__global__ void k_final_acc(const float* __restrict__ Wo, float* __restrict__ out) {
    __shared__ __align__(16) float sp[128][NGRAPH];
    __shared__ float sinv[NGRAPH];
    int tid = threadIdx.x;
    int c = blockIdx.x * 256 + tid;
    int k0 = blockIdx.y * 128;
    if (tid < NGRAPH) sinv[tid] = 1.0f / fmaxf(d_cnt[tid], 1.0f);
    for (int i = tid; i < 128 * NGRAPH; i += 256) {
        int k = i >> 4, g = i & 15;
        sp[k][g] = d_pool[(size_t)g * D3 + k0 + k];
    }
    __syncthreads();
    float acc[NGRAPH];
#pragma unroll
    for (int g = 0; g < NGRAPH; g++) acc[g] = 0.0f;
#pragma unroll 4
    for (int k = 0; k < 128; k++) {
        float w = Wo[(size_t)(k0 + k) * D3 + c];
        const float4* pr = (const float4*)sp[k];
#pragma unroll
        for (int q = 0; q < 4; q++) {
            float4 pv = pr[q];
            acc[q * 4 + 0] = fmaf(pv.x, w, acc[q * 4 + 0]);
            acc[q * 4 + 1] = fmaf(pv.y, w, acc[q * 4 + 1]);
            acc[q * 4 + 2] = fmaf(pv.z, w, acc[q * 4 + 2]);
            acc[q * 4 + 3] = fmaf(pv.w, w, acc[q * 4 + 3]);
        }
    }
#pragma unroll
    for (int g = 0; g < NGRAPH; g++)
        red_add_f32(&out[(size_t)g * D3 + c], acc[g] * sinv[g]);
}

// ---------------- launcher ----------------
extern "C" void kernel_launch(void* const* d_in, const int* in_sizes, int n_in,
                              void* d_out, int out_size) {
    const float *x, *W1, *b1, *W2, *b2, *W3, *b3, *Wo, *bo;
    const void *ei, *batch;
    if (in_sizes[0] == N_NODES) {           // dict order
        x     = (const float*)d_in[0];
        ei    = d_in[1];
        batch = d_in[2];
        W1 = (const float*)d_in[3];  b1 = (const float*)d_in[4];
        W2 = (const float*)d_in[5];  b2 = (const float*)d_in[6];
        W3 = (const float*)d_in[7];  b3 = (const float*)d_in[8];
        Wo = (const float*)d_in[9];  bo = (const float*)d_in[10];
    } else {                                // alphabetical order
        W1 = (const float*)d_in[0];
        W2 = (const float*)d_in[1];
        W3 = (const float*)d_in[2];
        Wo = (const float*)d_in[3];
        b1 = (const float*)d_in[4];
        b2 = (const float*)d_in[5];
        b3 = (const float*)d_in[6];
        batch = d_in[7];
        bo = (const float*)d_in[8];
        ei = d_in[9];
        x  = (const float*)d_in[10];
    }
    float* out = (float*)d_out;

    __half *a2h, *a3h, *b2h, *b3h;
    cudaGetSymbolAddress((void**)&a2h, d_a2h);
    cudaGetSymbolAddress((void**)&a3h, d_a3h);
    cudaGetSymbolAddress((void**)&b2h, d_b2h);
    cudaGetSymbolAddress((void**)&b3h, d_b3h);

    static int init_done = 0;
    static cudaStream_t s_side;
    static cudaEvent_t ev_fork, ev_join, ev_fill, ev_g1b, ev_g2done, ev_g2b;
    if (!init_done) {
        cudaFuncSetAttribute(mma_gemm, cudaFuncAttributeMaxDynamicSharedMemorySize, 98304);
        cudaStreamCreateWithFlags(&s_side, cudaStreamNonBlocking);
        cudaEventCreateWithFlags(&ev_fork, cudaEventDisableTiming);
        cudaEventCreateWithFlags(&ev_join, cudaEventDisableTiming);
        cudaEventCreateWithFlags(&ev_fill, cudaEventDisableTiming);
        cudaEventCreateWithFlags(&ev_g1b, cudaEventDisableTiming);
        cudaEventCreateWithFlags(&ev_g2done, cudaEventDisableTiming);
        cudaEventCreateWithFlags(&ev_g2b, cudaEventDisableTiming);
        init_done = 1;
    }

    const int TB = 256;
    int nb_nodes = (N_NODES + TB - 1) / TB;
    int nb_deg   = (N_EDGES + TB * 4 - 1) / (TB * 4);
    int nb_fill  = (N_EDGES + TB * 2 - 1) / (TB * 2);

    const int g1_blocks_h1 = (N_NODES - ROWS_H0 + 7) / 8;   // 1878
    const int gemm_rows_h0 = ROWS_H0 / 128;                  // 117
    const int gemm_rows_h1 = (N_NODES - ROWS_H0 + 127) / 128; // 118

    // fork: weight conversions on the side stream
    cudaEventRecord(ev_fork, 0);
    cudaStreamWaitEvent(s_side, ev_fork, 0);
    {
        dim3 g2w(D2 / 32, D1 / 32);
        k_wconv<<<g2w, 256, 0, s_side>>>(W2, b2h, D1, D2);
        dim3 g3w(D3 / 32, D2 / 32);
        k_wconv<<<g3w, 256, 0, s_side>>>(W3, b3h, D2, D3);
    }
    cudaEventRecord(ev_join, s_side);

    // main chain: setup
    k_init<<<nb_nodes, TB>>>(ei, bo, out);
    k_deg_cnt<<<nb_deg, TB>>>(ei, batch);
    k_dis_s1<<<nb_nodes, TB>>>(x);
    k_fill<<<nb_fill, TB>>>(ei, x);
    cudaEventRecord(ev_fill, 0);

    // gather1 pipelined: h1 on side, h0 on main, GEMM2_h0 overlaps gather1_h1
    cudaStreamWaitEvent(s_side, ev_fill, 0);
    k_gather1<<<g1_blocks_h1, TB, 0, s_side>>>(W1, b1, ROWS_H0);
    cudaEventRecord(ev_g1b, s_side);

    k_gather1<<<NODE8_H0, TB>>>(W1, b1, 0);
    cudaStreamWaitEvent(0, ev_join, 0);
    {
        dim3 grid(D2 / 128, gemm_rows_h0);
        mma_gemm<<<grid, 256, 98304>>>(a2h, b2h, b2, nullptr, N_NODES, D2, D1, 0, 0);
    }
    cudaStreamWaitEvent(0, ev_g1b, 0);
    {
        dim3 grid(D2 / 128, gemm_rows_h1);
        mma_gemm<<<grid, 256, 98304>>>(a2h, b2h, b2, nullptr, N_NODES, D2, D1, 0, ROWS_H0);
    }
    cudaEventRecord(ev_g2done, 0);

    // gather2 pipelined: h1 on side, h0 on main, GEMM3_h0 overlaps gather2_h1
    cudaStreamWaitEvent(s_side, ev_g2done, 0);
    k_gather2<<<g1_blocks_h1, TB, 0, s_side>>>(ROWS_H0);
    cudaEventRecord(ev_g2b, s_side);

    k_gather2<<<NODE8_H0, TB>>>(0);
    {
        dim3 grid(D3 / 128, gemm_rows_h0);
        mma_gemm<<<grid, 256, 98304>>>(a3h, b3h, b3, batch, N_NODES, D3, D2, 1, 0);
    }
    cudaStreamWaitEvent(0, ev_g2b, 0);
    {
        dim3 grid(D3 / 128, gemm_rows_h1);
        mma_gemm<<<grid, 256, 98304>>>(a3h, b3h, b3, batch, N_NODES, D3, D2, 1, ROWS_H0);
    }

    // final linear, K-split across 32 blocks
    {
        dim3 grid(4, 8);
        k_final_acc<<<grid, 256>>>(Wo, out);
    }
}

// round 16
// speedup vs baseline: 1.0602x; 1.0602x over previous
#include <cuda_runtime.h>
#include <cuda_fp16.h>
#include <cstdint>

#define N_NODES 30000
#define N_EDGES 240000
#define NGRAPH  16
#define D1      256
#define D2      512
#define D3      1024

// ---------------- scratch (no allocations allowed) ----------------
__device__ int   d_idx64;            // 1 if indices are int64, 0 if int32
__device__ int   d_alloc;            // CSR segment allocator
__device__ int   d_cin[N_NODES];     // in-degree (edges only)
__device__ int   d_rowptr[N_NODES];  // segment start per node (arbitrary order)
__device__ int   d_cursor[N_NODES];
__device__ __align__(16) int2 d_epay[N_EDGES];      // (src, norm-bits) CSR payload
__device__ float d_dis[N_NODES];
__device__ float d_s1 [N_NODES];
__device__ __align__(16) float d_pool[NGRAPH * D3];
__device__ float d_cnt[NGRAPH];

// fp16 operand & activation buffers
__device__ __align__(16) __half d_a2h[N_NODES * D1];
__device__ __align__(16) __half d_h2h[N_NODES * D2];
__device__ __align__(16) __half d_a3h[N_NODES * D2];
__device__ __align__(16) __half d_b2h[D2 * D1];   // [N=512, K=256] K-major
__device__ __align__(16) __half d_b3h[D3 * D2];   // [N=1024, K=512] K-major

// ---------------- small helpers ----------------
__device__ __forceinline__ int load_idx(const void* p, int i) {
    if (d_idx64) return (int)((const long long*)p)[i];
    return ((const int*)p)[i];
}
__device__ __forceinline__ void red_add_f32(float* p, float v) {
    asm volatile("red.global.add.f32 [%0], %1;" :: "l"(p), "f"(v) : "memory");
}
__device__ __forceinline__ void red_add_v2(float* p, float x, float y) {
    asm volatile("red.global.add.v2.f32 [%0], {%1,%2};"
                 :: "l"(p), "f"(x), "f"(y) : "memory");
}
__device__ __forceinline__ uint32_t smem_u32(const void* p) {
    uint32_t a;
    asm("{ .reg .u64 t; cvta.to.shared.u64 t, %1; cvt.u32.u64 %0, t; }" : "=r"(a) : "l"(p));
    return a;
}
__device__ __forceinline__ void ldm_x4(uint32_t* r, uint32_t addr) {
    asm volatile("ldmatrix.sync.aligned.m8n8.x4.shared.b16 {%0,%1,%2,%3}, [%4];"
                 : "=r"(r[0]), "=r"(r[1]), "=r"(r[2]), "=r"(r[3]) : "r"(addr));
}
__device__ __forceinline__ void cp_async16(uint32_t dst, const void* src, uint32_t srcsize) {
    asm volatile("cp.async.cg.shared.global [%0], [%1], 16, %2;"
                 :: "r"(dst), "l"(src), "r"(srcsize) : "memory");
}
__device__ __forceinline__ void cp_commit(void) {
    asm volatile("cp.async.commit_group;" ::: "memory");
}
__device__ __forceinline__ void mma16816(float* c, const uint32_t* a, uint32_t b0, uint32_t b1) {
    asm volatile(
        "mma.sync.aligned.m16n8k16.row.col.f32.f16.f16.f32 "
        "{%0,%1,%2,%3}, {%4,%5,%6,%7}, {%8,%9}, {%0,%1,%2,%3};"
        : "+f"(c[0]), "+f"(c[1]), "+f"(c[2]), "+f"(c[3])
        : "r"(a[0]), "r"(a[1]), "r"(a[2]), "r"(a[3]), "r"(b0), "r"(b1));
}
__device__ __forceinline__ float2 h2f2(uint32_t u) {
    __half2 h = *reinterpret_cast<__half2*>(&u);
    return __half22float2(h);
}
__device__ __forceinline__ uint32_t f2h2(float a, float b) {
    __half2 h = __floats2half2_rn(a, b);
    return *reinterpret_cast<uint32_t*>(&h);
}

// ---------------- setup (init + dtype detect + out-bias init fused) ----------------
__global__ void k_init(const void* __restrict__ ei, const float* __restrict__ bo,
                       float* __restrict__ out) {
    int i = blockIdx.x * blockDim.x + threadIdx.x;
    if (i < N_NODES) d_cin[i] = 0;
    if (i < NGRAPH) d_cnt[i] = 0.0f;
    if (i < NGRAPH * D3) {
        d_pool[i] = 0.0f;
        out[i] = bo[i & (D3 - 1)];
    }
    if (i == 0) {
        d_alloc = 0;
        const long long* p = (const long long*)ei;
        int ok = 1;
        for (int j = 0; j < 64; j++) {
            long long v = p[j];
            if (v < 0 || v >= N_NODES) { ok = 0; break; }
        }
        d_idx64 = ok;
    }
}

// in-degree + batch count, 4 items/thread (MLP=4), warp-aggregated cnt atomics
__global__ void k_deg_cnt(const void* __restrict__ ei, const void* __restrict__ batch) {
    int base = (blockIdx.x * blockDim.x + threadIdx.x) * 4;

    int dst[4];
#pragma unroll
    for (int j = 0; j < 4; j++) {
        int e = base + j;
        dst[j] = (e < N_EDGES) ? load_idx(ei, N_EDGES + e) : -1;
    }
#pragma unroll
    for (int j = 0; j < 4; j++)
        if (dst[j] >= 0) atomicAdd(&d_cin[dst[j]], 1);

    int g0 = -1, c0 = 0, g1 = -1, c1 = 0;
#pragma unroll
    for (int j = 0; j < 4; j++) {
        int i = base + j;
        if (i >= N_NODES) break;
        int g = load_idx(batch, i);
        if (g == g0) c0++;
        else if (g == g1) c1++;
        else if (g0 < 0) { g0 = g; c0 = 1; }
        else if (g1 < 0) { g1 = g; c1 = 1; }
        else atomicAdd(&d_cnt[g], 1.0f);
    }
    unsigned am = __activemask();
    if (g0 >= 0) {
        unsigned m = __match_any_sync(am, g0);
        float sum = (float)c0;
        for (int off = 16; off; off >>= 1) {
            float v = __shfl_down_sync(am, sum, off);
            int src = (threadIdx.x & 31) + off;
            if ((m >> src) & 1) sum += v;
        }
        if ((threadIdx.x & 31) == (__ffs(m) - 1)) atomicAdd(&d_cnt[g0], sum);
    }
    if (g1 >= 0) atomicAdd(&d_cnt[g1], (float)c1);
}

// dis/s1 + CSR segment allocation (warp-aggregated atomic, order-free)
__global__ void k_dis_s1(const float* __restrict__ x) {
    int i = blockIdx.x * blockDim.x + threadIdx.x;
    int lane = threadIdx.x & 31;
    int valid = (i < N_NODES);
    int c = valid ? d_cin[i] : 0;
    if (valid) {
        float r = rsqrtf((float)(c + 1));
        d_dis[i] = r;
        d_s1[i]  = r * r * x[i];
    }
    unsigned mask = 0xffffffffu;
    int incl = c;
#pragma unroll
    for (int off = 1; off < 32; off <<= 1) {
        int v = __shfl_up_sync(mask, incl, off);
        if (lane >= off) incl += v;
    }
    int total = __shfl_sync(mask, incl, 31);
    int base = 0;
    if (lane == 31) base = atomicAdd(&d_alloc, total);
    base = __shfl_sync(mask, base, 31);
    if (valid) {
        int start = base + incl - c;
        d_rowptr[i] = start;
        d_cursor[i] = start;
    }
}

// CSR fill + edge contribution to s1, 2 edges/thread (MLP)
__global__ void k_fill(const void* __restrict__ ei, const float* __restrict__ x) {
    int base = (blockIdx.x * blockDim.x + threadIdx.x) * 2;
    int s[2], d[2];
#pragma unroll
    for (int j = 0; j < 2; j++) {
        int e = base + j;
        if (e < N_EDGES) { s[j] = load_idx(ei, e); d[j] = load_idx(ei, N_EDGES + e); }
        else { s[j] = -1; d[j] = 0; }
    }
    float ds[2], dd[2], xs[2];
#pragma unroll
    for (int j = 0; j < 2; j++) {
        if (s[j] >= 0) { ds[j] = d_dis[s[j]]; dd[j] = d_dis[d[j]]; xs[j] = x[s[j]]; }
    }
#pragma unroll
    for (int j = 0; j < 2; j++) {
        if (s[j] < 0) continue;
        float nv = ds[j] * dd[j];
        int pos = atomicAdd(&d_cursor[d[j]], 1);
        d_epay[pos] = make_int2(s[j], __float_as_int(nv));
        atomicAdd(&d_s1[d[j]], nv * xs[j]);
    }
}

// ---------------- layer 1 gather: a2 = fp16(A_hat @ h1), h1 rank-1 on the fly ----------------
__global__ __launch_bounds__(256)
void k_gather1(const float* __restrict__ W1, const float* __restrict__ b1) {
    __shared__ float sW[D1], sB[D1];
    int tid = threadIdx.x;
    if (tid < D1) { sW[tid] = W1[tid]; sB[tid] = b1[tid]; }
    __syncthreads();
    int warp = tid >> 5, lane = tid & 31;
    int node = blockIdx.x * 8 + warp;
    if (node >= N_NODES) return;
    float w[8], b[8];
#pragma unroll
    for (int q = 0; q < 8; q++) { w[q] = sW[lane * 8 + q]; b[q] = sB[lane * 8 + q]; }
    float acc[8];
    float dis = d_dis[node];
    float coef = dis * dis, sv = d_s1[node];
#pragma unroll
    for (int q = 0; q < 8; q++) acc[q] = coef * fmaxf(fmaf(sv, w[q], b[q]), 0.0f);
    int beg = d_rowptr[node], end = beg + d_cin[node];
    for (int e = beg; e < end; e++) {
        int2 pay = d_epay[e];
        float nv = __int_as_float(pay.y);
        float s = d_s1[pay.x];
#pragma unroll
        for (int q = 0; q < 8; q++) acc[q] = fmaf(nv, fmaxf(fmaf(s, w[q], b[q]), 0.0f), acc[q]);
    }
    uint32_t hw[4];
#pragma unroll
    for (int q2 = 0; q2 < 4; q2++) hw[q2] = f2h2(acc[q2 * 2], acc[q2 * 2 + 1]);
    size_t off = (size_t)node * D1 + lane * 8;
    *(uint4*)(d_a2h + off) = make_uint4(hw[0], hw[1], hw[2], hw[3]);
}

// ---------------- layer 2 gather: a3 = fp16(A_hat @ h2), h2 stored fp16 ----------------
__device__ __forceinline__ void acc_row16(float* acc, int row, float nv, int lane) {
    size_t off = (size_t)row * D2 + lane * 16;
    uint4 h0 = *(const uint4*)(d_h2h + off);
    uint4 h1 = *(const uint4*)(d_h2h + off + 8);
    const uint32_t hu[8] = {h0.x, h0.y, h0.z, h0.w, h1.x, h1.y, h1.z, h1.w};
#pragma unroll
    for (int q = 0; q < 8; q++) {
        float2 hv = h2f2(hu[q]);
        acc[q * 2 + 0] = fmaf(nv, hv.x, acc[q * 2 + 0]);
        acc[q * 2 + 1] = fmaf(nv, hv.y, acc[q * 2 + 1]);
    }
}

__global__ __launch_bounds__(256)
void k_gather2(void) {
    int tid = threadIdx.x;
    int warp = tid >> 5, lane = tid & 31;
    int node = blockIdx.x * 8 + warp;
    if (node >= N_NODES) return;
    float acc[16];
#pragma unroll
    for (int q = 0; q < 16; q++) acc[q] = 0.0f;
    float dis = d_dis[node];
    acc_row16(acc, node, dis * dis, lane);
    int beg = d_rowptr[node], end = beg + d_cin[node];
    for (int e = beg; e < end; e++) {
        int2 pay = d_epay[e];
        acc_row16(acc, pay.x, __int_as_float(pay.y), lane);
    }
    uint32_t hw[8];
#pragma unroll
    for (int q2 = 0; q2 < 8; q2++) hw[q2] = f2h2(acc[q2 * 2], acc[q2 * 2 + 1]);
    size_t off = (size_t)node * D2 + lane * 16;
    *(uint4*)(d_a3h + off)     = make_uint4(hw[0], hw[1], hw[2], hw[3]);
    *(uint4*)(d_a3h + off + 8) = make_uint4(hw[4], hw[5], hw[6], hw[7]);
}

// W [K, N] fp32 row-major -> B [N, K] fp16 (transposed, K-major), tiled/coalesced
__global__ __launch_bounds__(256)
void k_wconv(const float* __restrict__ W, __half* __restrict__ bh, int K, int N) {
    __shared__ float tile[32][33];
    int n0 = blockIdx.x * 32, k0 = blockIdx.y * 32;
    int tx = threadIdx.x & 31, ty = threadIdx.x >> 5;   // 32 x 8
#pragma unroll
    for (int j = 0; j < 32; j += 8)
        tile[ty + j][tx] = W[(size_t)(k0 + ty + j) * N + n0 + tx];
    __syncthreads();
#pragma unroll
    for (int j = 0; j < 32; j += 8)
        bh[(size_t)(n0 + ty + j) * K + k0 + tx] = __float2half_rn(tile[tx][ty + j]);
}

// ---------------- fp16 GEMM: ldmatrix + 3-stage cp.async pipeline, 1 sync/chunk ----------------
// mode 0: h2 = relu(D+bias) stored as fp16                  (layer 2)
// mode 1: relu(D+bias) pooled into d_pool[batch]            (layer 3)
__global__ __launch_bounds__(256, 2)
void mma_gemm(const __half* __restrict__ A, const __half* __restrict__ B,
              const float* __restrict__ bias, const void* __restrict__ batch,
              int M, int Nglob, int K, int mode) {
    extern __shared__ __align__(16) char dynsm[];

    const int tid = threadIdx.x;
    const int wid = tid >> 5, lane = tid & 31;
    const int g = lane >> 2, tig = lane & 3;
    const int warp_m = wid & 3, warp_n = wid >> 2;
    const int row0 = blockIdx.y * 128, col0 = blockIdx.x * 128;
    const int mr = warp_m * 32, nc = warp_n * 64;

    const int t   = lane >> 3;
    const int thi = t >> 1;
    const int rlo = (t & 1) * 8 + (lane & 7);

    const uint32_t smbase = smem_u32(dynsm);
    const uint32_t stA[3] = { smbase, smbase + 32768u, smbase + 65536u };
    const uint32_t stB[3] = { smbase + 16384u, smbase + 49152u, smbase + 81920u };

    int rA0 = mr + rlo, rA1 = mr + 16 + rlo;
    uint32_t aoff0 = (uint32_t)(rA0 * 128), amask0 = (uint32_t)(rA0 & 7);
    uint32_t aoff1 = (uint32_t)(rA1 * 128), amask1 = (uint32_t)(rA1 & 7);
    uint32_t boff[4], bmask[4];
#pragma unroll
    for (int p = 0; p < 4; p++) {
        int rB = nc + p * 16 + rlo;
        boff[p] = (uint32_t)(rB * 128);
        bmask[p] = (uint32_t)(rB & 7);
    }

    float acc[2][8][4];
#pragma unroll
    for (int mf = 0; mf < 2; mf++)
#pragma unroll
        for (int nf = 0; nf < 8; nf++)
#pragma unroll
            for (int q = 0; q < 4; q++) acc[mf][nf][q] = 0.0f;

    const int nk = K >> 6;

    const int lr = tid >> 1;
    const int lc2 = (tid & 1) * 4;
    auto prefetch = [&](int kc, int s) {
        const int kof = kc << 6;
        int grow = row0 + lr;
        uint32_t asz = (grow < M) ? 16u : 0u;
        const __half* agp = A + (size_t)grow * K + kof + lc2 * 8;
        const __half* bgp = B + (size_t)(col0 + lr) * K + kof + lc2 * 8;
        uint32_t arow = (uint32_t)(lr * 128);
#pragma unroll
        for (int j = 0; j < 4; j++) {
            int ch = lc2 + j;
            uint32_t soff = arow + (uint32_t)(((ch ^ (lr & 7)) << 4));
            cp_async16(stA[s] + soff, agp + j * 8, asz);
            cp_async16(stB[s] + soff, bgp + j * 8, 16u);
        }
        cp_commit();
    };

    prefetch(0, 0);
    if (nk > 1) prefetch(1, 1);
    int sidx = 0;
    for (int kc = 0; kc < nk; kc++) {
        if (kc == nk - 1) {
            asm volatile("cp.async.wait_group 0;" ::: "memory");
        } else {
            asm volatile("cp.async.wait_group 1;" ::: "memory");
        }
        __syncthreads();
        if (kc + 2 < nk) prefetch(kc + 2, (sidx + 2) % 3);
        const int s = sidx;

#pragma unroll
        for (int ks = 0; ks < 4; ks++) {
            const uint32_t kg = (uint32_t)(2 * ks + thi);
            uint32_t a0[4], a1[4];
            ldm_x4(a0, stA[s] + aoff0 + (((kg ^ amask0) << 4)));
            ldm_x4(a1, stA[s] + aoff1 + (((kg ^ amask1) << 4)));
#pragma unroll
            for (int p = 0; p < 4; p++) {
                uint32_t bf[4];
                ldm_x4(bf, stB[s] + boff[p] + (((kg ^ bmask[p]) << 4)));
                mma16816(acc[0][2 * p + 0], a0, bf[0], bf[2]);
                mma16816(acc[0][2 * p + 1], a0, bf[1], bf[3]);
                mma16816(acc[1][2 * p + 0], a1, bf[0], bf[2]);
                mma16816(acc[1][2 * p + 1], a1, bf[1], bf[3]);
            }
        }
        sidx = (sidx + 1) % 3;
    }

    // ---------------- epilogue ----------------
    if (mode == 0) {
#pragma unroll
        for (int mf = 0; mf < 2; mf++) {
#pragma unroll
            for (int half = 0; half < 2; half++) {
                int row = row0 + mr + mf * 16 + g + half * 8;
                if (row >= M) continue;
#pragma unroll
                for (int nf = 0; nf < 8; nf++) {
                    int col = col0 + nc + nf * 8 + tig * 2;
                    float2 bv = *(const float2*)&bias[col];
                    float v0 = fmaxf(acc[mf][nf][half * 2 + 0] + bv.x, 0.0f);
                    float v1 = fmaxf(acc[mf][nf][half * 2 + 1] + bv.y, 0.0f);
                    *(uint32_t*)(d_h2h + (size_t)row * D2 + col) = f2h2(v0, v1);
                }
            }
        }
    } else {
#pragma unroll
        for (int mf = 0; mf < 2; mf++) {
            int ra = row0 + mr + mf * 16 + g;
            int v0ok = (ra < M), v1ok = (ra + 8 < M);
#pragma unroll
            for (int nf = 0; nf < 8; nf++) {
                int col = col0 + nc + nf * 8 + tig * 2;
                float2 bv = *(const float2*)&bias[col];
                acc[mf][nf][0] = v0ok ? fmaxf(acc[mf][nf][0] + bv.x, 0.0f) : 0.0f;
                acc[mf][nf][1] = v0ok ? fmaxf(acc[mf][nf][1] + bv.y, 0.0f) : 0.0f;
                acc[mf][nf][2] = v1ok ? fmaxf(acc[mf][nf][2] + bv.x, 0.0f) : 0.0f;
                acc[mf][nf][3] = v1ok ? fmaxf(acc[mf][nf][3] + bv.y, 0.0f) : 0.0f;
            }
        }
        unsigned mask = 0xffffffffu;
        int rv = row0 + mr + lane;
        int bl = (rv < N_NODES) ? load_idx(batch, rv) : -1;
        int b0 = __shfl_sync(mask, bl, 0);
        bool uni = __all_sync(mask, bl == b0);
        if (uni && b0 >= 0) {
            float s[8][2];
#pragma unroll
            for (int nf = 0; nf < 8; nf++) {
                s[nf][0] = acc[0][nf][0] + acc[0][nf][2] + acc[1][nf][0] + acc[1][nf][2];
                s[nf][1] = acc[0][nf][1] + acc[0][nf][3] + acc[1][nf][1] + acc[1][nf][3];
            }
#pragma unroll
            for (int off = 4; off < 32; off <<= 1)
#pragma unroll
                for (int nf = 0; nf < 8; nf++) {
                    s[nf][0] += __shfl_xor_sync(mask, s[nf][0], off);
                    s[nf][1] += __shfl_xor_sync(mask, s[nf][1], off);
                }
            if (lane < 4) {
#pragma unroll
                for (int nf = 0; nf < 8; nf++) {
                    int col = col0 + nc + nf * 8 + lane * 2;
                    red_add_v2(&d_pool[(size_t)b0 * D3 + col], s[nf][0], s[nf][1]);
                }
            }
        } else {
#pragma unroll
            for (int mf = 0; mf < 2; mf++)
#pragma unroll
                for (int half = 0; half < 2; half++) {
                    int row = row0 + mr + mf * 16 + g + half * 8;
                    if (row >= M) continue;
                    int gb = load_idx(batch, row);
#pragma unroll
                    for (int nf = 0; nf < 8; nf++) {
                        int col = col0 + nc + nf * 8 + tig * 2;
                        red_add_v2(&d_pool[(size_t)gb * D3 + col],
                                   acc[mf][nf][half * 2], acc[mf][nf][half * 2 + 1]);
                    }
                }
        }
    }
}

// ---------------- final linear [16,1024] @ [1024,1024], K-split + atomics ----------------
__global__ void k_final_acc(const float* __restrict__ Wo, float* __restrict__ out) {
    __shared__ __align__(16) float sp[128][NGRAPH];
    __shared__ float sinv[NGRAPH];
    int tid = threadIdx.x;
    int c = blockIdx.x * 256 + tid;
    int k0 = blockIdx.y * 128;
    if (tid < NGRAPH) sinv[tid] = 1.0f / fmaxf(d_cnt[tid], 1.0f);
    for (int i = tid; i < 128 * NGRAPH; i += 256) {
        int k = i >> 4, g = i & 15;
        sp[k][g] = d_pool[(size_t)g * D3 + k0 + k];
    }
    __syncthreads();
    float acc[NGRAPH];
#pragma unroll
    for (int g = 0; g < NGRAPH; g++) acc[g] = 0.0f;
#pragma unroll 4
    for (int k = 0; k < 128; k++) {
        float w = Wo[(size_t)(k0 + k) * D3 + c];
        const float4* pr = (const float4*)sp[k];
#pragma unroll
        for (int q = 0; q < 4; q++) {
            float4 pv = pr[q];
            acc[q * 4 + 0] = fmaf(pv.x, w, acc[q * 4 + 0]);
            acc[q * 4 + 1] = fmaf(pv.y, w, acc[q * 4 + 1]);
            acc[q * 4 + 2] = fmaf(pv.z, w, acc[q * 4 + 2]);
            acc[q * 4 + 3] = fmaf(pv.w, w, acc[q * 4 + 3]);
        }
    }
#pragma unroll
    for (int g = 0; g < NGRAPH; g++)
        red_add_f32(&out[(size_t)g * D3 + c], acc[g] * sinv[g]);
}

// ---------------- launcher ----------------
extern "C" void kernel_launch(void* const* d_in, const int* in_sizes, int n_in,
                              void* d_out, int out_size) {
    const float *x, *W1, *b1, *W2, *b2, *W3, *b3, *Wo, *bo;
    const void *ei, *batch;
    if (in_sizes[0] == N_NODES) {           // dict order
        x     = (const float*)d_in[0];
        ei    = d_in[1];
        batch = d_in[2];
        W1 = (const float*)d_in[3];  b1 = (const float*)d_in[4];
        W2 = (const float*)d_in[5];  b2 = (const float*)d_in[6];
        W3 = (const float*)d_in[7];  b3 = (const float*)d_in[8];
        Wo = (const float*)d_in[9];  bo = (const float*)d_in[10];
    } else {                                // alphabetical order
        W1 = (const float*)d_in[0];
        W2 = (const float*)d_in[1];
        W3 = (const float*)d_in[2];
        Wo = (const float*)d_in[3];
        b1 = (const float*)d_in[4];
        b2 = (const float*)d_in[5];
        b3 = (const float*)d_in[6];
        batch = d_in[7];
        bo = (const float*)d_in[8];
        ei = d_in[9];
        x  = (const float*)d_in[10];
    }
    float* out = (float*)d_out;

    __half *a2h, *a3h, *b2h, *b3h;
    cudaGetSymbolAddress((void**)&a2h, d_a2h);
    cudaGetSymbolAddress((void**)&a3h, d_a3h);
    cudaGetSymbolAddress((void**)&b2h, d_b2h);
    cudaGetSymbolAddress((void**)&b3h, d_b3h);

    static int init_done = 0;
    static cudaStream_t s_side;
    static cudaEvent_t ev_fork, ev_join;
    if (!init_done) {
        cudaFuncSetAttribute(mma_gemm, cudaFuncAttributeMaxDynamicSharedMemorySize, 98304);
        cudaStreamCreateWithFlags(&s_side, cudaStreamNonBlocking);
        cudaEventCreateWithFlags(&ev_fork, cudaEventDisableTiming);
        cudaEventCreateWithFlags(&ev_join, cudaEventDisableTiming);
        init_done = 1;
    }

    const int TB = 256;
    int nb_nodes = (N_NODES + TB - 1) / TB;
    int nb_deg   = (N_EDGES + TB * 4 - 1) / (TB * 4);
    int nb_fill  = (N_EDGES + TB * 2 - 1) / (TB * 2);
    int nb_node8 = (N_NODES + 7) / 8;

    // fork: weight conversions on the side stream, overlapped with graph setup
    cudaEventRecord(ev_fork, 0);
    cudaStreamWaitEvent(s_side, ev_fork, 0);
    {
        dim3 g2w(D2 / 32, D1 / 32);
        k_wconv<<<g2w, 256, 0, s_side>>>(W2, b2h, D1, D2);
        dim3 g3w(D3 / 32, D2 / 32);
        k_wconv<<<g3w, 256, 0, s_side>>>(W3, b3h, D2, D3);
    }
    cudaEventRecord(ev_join, s_side);

    // main chain
    k_init<<<nb_nodes, TB>>>(ei, bo, out);
    k_deg_cnt<<<nb_deg, TB>>>(ei, batch);
    k_dis_s1<<<nb_nodes, TB>>>(x);
    k_fill<<<nb_fill, TB>>>(ei, x);
    k_gather1<<<nb_node8, TB>>>(W1, b1);

    // join weight conversions before first GEMM
    cudaStreamWaitEvent(0, ev_join, 0);

    // layer 2 GEMM: h2 = relu(a2 @ W2 + b2) stored fp16
    {
        dim3 grid(D2 / 128, (N_NODES + 127) / 128);
        mma_gemm<<<grid, 256, 98304>>>(a2h, b2h, b2, nullptr, N_NODES, D2, D1, 0);
    }

    // layer 2 aggregation: gather, emit a3 fp16 directly
    k_gather2<<<nb_node8, TB>>>();

    // layer 3 GEMM with fused pooling
    {
        dim3 grid(D3 / 128, (N_NODES + 127) / 128);
        mma_gemm<<<grid, 256, 98304>>>(a3h, b3h, b3, batch, N_NODES, D3, D2, 1);
    }

    // final linear, K-split across 32 blocks
    {
        dim3 grid(4, 8);
        k_final_acc<<<grid, 256>>>(Wo, out);
    }
}

// round 17
// speedup vs baseline: 1.0785x; 1.0172x over previous
#include <cuda_runtime.h>
#include <cuda_fp16.h>
#include <cstdint>

#define N_NODES 30000
#define N_EDGES 240000
#define NGRAPH  16
#define D1      256
#define D2      512
#define D3      1024

// ---------------- scratch (no allocations allowed) ----------------
__device__ int   d_idx64;            // 1 if indices are int64, 0 if int32
__device__ int   d_alloc;            // CSR segment allocator
__device__ int   d_cin[N_NODES];     // in-degree (edges only)
__device__ int   d_rowptr[N_NODES];  // segment start per node (arbitrary order)
__device__ int   d_cursor[N_NODES];
__device__ __align__(16) int2 d_epay[N_EDGES];      // (src, norm-bits) CSR payload
__device__ float d_dis[N_NODES];
__device__ float d_s1 [N_NODES];
__device__ __align__(16) float d_pool[NGRAPH * D3];
__device__ float d_cnt[NGRAPH];

// fp16 operand & activation buffers
__device__ __align__(16) __half d_a2h[N_NODES * D1];
__device__ __align__(16) __half d_h2h[N_NODES * D2];
__device__ __align__(16) __half d_a3h[N_NODES * D2];
__device__ __align__(16) __half d_b2h[D2 * D1];   // [N=512, K=256] K-major
__device__ __align__(16) __half d_b3h[D3 * D2];   // [N=1024, K=512] K-major

// ---------------- small helpers ----------------
__device__ __forceinline__ int load_idx(const void* p, int i) {
    if (d_idx64) return (int)((const long long*)p)[i];
    return ((const int*)p)[i];
}
__device__ __forceinline__ void red_add_f32(float* p, float v) {
    asm volatile("red.global.add.f32 [%0], %1;" :: "l"(p), "f"(v) : "memory");
}
__device__ __forceinline__ void red_add_v2(float* p, float x, float y) {
    asm volatile("red.global.add.v2.f32 [%0], {%1,%2};"
                 :: "l"(p), "f"(x), "f"(y) : "memory");
}
__device__ __forceinline__ uint32_t smem_u32(const void* p) {
    uint32_t a;
    asm("{ .reg .u64 t; cvta.to.shared.u64 t, %1; cvt.u32.u64 %0, t; }" : "=r"(a) : "l"(p));
    return a;
}
__device__ __forceinline__ void ldm_x4(uint32_t* r, uint32_t addr) {
    asm volatile("ldmatrix.sync.aligned.m8n8.x4.shared.b16 {%0,%1,%2,%3}, [%4];"
                 : "=r"(r[0]), "=r"(r[1]), "=r"(r[2]), "=r"(r[3]) : "r"(addr));
}
__device__ __forceinline__ void cp_async16(uint32_t dst, const void* src, uint32_t srcsize) {
    asm volatile("cp.async.cg.shared.global [%0], [%1], 16, %2;"
                 :: "r"(dst), "l"(src), "r"(srcsize) : "memory");
}
__device__ __forceinline__ void cp_commit(void) {
    asm volatile("cp.async.commit_group;" ::: "memory");
}
__device__ __forceinline__ void mma16816(float* c, const uint32_t* a, uint32_t b0, uint32_t b1) {
    asm volatile(
        "mma.sync.aligned.m16n8k16.row.col.f32.f16.f16.f32 "
        "{%0,%1,%2,%3}, {%4,%5,%6,%7}, {%8,%9}, {%0,%1,%2,%3};"
        : "+f"(c[0]), "+f"(c[1]), "+f"(c[2]), "+f"(c[3])
        : "r"(a[0]), "r"(a[1]), "r"(a[2]), "r"(a[3]), "r"(b0), "r"(b1));
}
__device__ __forceinline__ float2 h2f2(uint32_t u) {
    __half2 h = *reinterpret_cast<__half2*>(&u);
    return __half22float2(h);
}
__device__ __forceinline__ uint32_t f2h2(float a, float b) {
    __half2 h = __floats2half2_rn(a, b);
    return *reinterpret_cast<uint32_t*>(&h);
}

// ---------------- setup (init + dtype detect + out-bias init fused) ----------------
__global__ void k_init(const void* __restrict__ ei, const float* __restrict__ bo,
                       float* __restrict__ out) {
    int i = blockIdx.x * blockDim.x + threadIdx.x;
    if (i < N_NODES) d_cin[i] = 0;
    if (i < NGRAPH) d_cnt[i] = 0.0f;
    if (i < NGRAPH * D3) {
        d_pool[i] = 0.0f;
        out[i] = bo[i & (D3 - 1)];
    }
    if (i == 0) {
        d_alloc = 0;
        const long long* p = (const long long*)ei;
        int ok = 1;
        for (int j = 0; j < 64; j++) {
            long long v = p[j];
            if (v < 0 || v >= N_NODES) { ok = 0; break; }
        }
        d_idx64 = ok;
    }
}

// in-degree + batch count, 8 items/thread (MLP=8), warp-aggregated cnt atomics
__global__ void k_deg_cnt(const void* __restrict__ ei, const void* __restrict__ batch) {
    int base = (blockIdx.x * blockDim.x + threadIdx.x) * 8;

    int dst[8];
#pragma unroll
    for (int j = 0; j < 8; j++) {
        int e = base + j;
        dst[j] = (e < N_EDGES) ? load_idx(ei, N_EDGES + e) : -1;
    }
#pragma unroll
    for (int j = 0; j < 8; j++)
        if (dst[j] >= 0) atomicAdd(&d_cin[dst[j]], 1);

    // batch counts: run aggregation over 8 sorted ids (<=2 runs typical)
    int g0 = -1, c0 = 0, g1 = -1, c1 = 0;
#pragma unroll
    for (int j = 0; j < 8; j++) {
        int i = base + j;
        if (i >= N_NODES) break;
        int g = load_idx(batch, i);
        if (g == g0) c0++;
        else if (g == g1) c1++;
        else if (g0 < 0) { g0 = g; c0 = 1; }
        else if (g1 < 0) { g1 = g; c1 = 1; }
        else atomicAdd(&d_cnt[g], 1.0f);    // >2 distinct in an 8-run: very rare
    }
    unsigned am = __activemask();
    if (g0 >= 0) {
        unsigned m = __match_any_sync(am, g0);
        float sum = (float)c0;
        for (int off = 16; off; off >>= 1) {
            float v = __shfl_down_sync(am, sum, off);
            int src = (threadIdx.x & 31) + off;
            if ((m >> src) & 1) sum += v;
        }
        if ((threadIdx.x & 31) == (__ffs(m) - 1)) atomicAdd(&d_cnt[g0], sum);
    }
    if (g1 >= 0) atomicAdd(&d_cnt[g1], (float)c1);
}

// dis/s1 + CSR segment allocation (warp-aggregated atomic, order-free)
__global__ void k_dis_s1(const float* __restrict__ x) {
    int i = blockIdx.x * blockDim.x + threadIdx.x;
    int lane = threadIdx.x & 31;
    int valid = (i < N_NODES);
    int c = valid ? d_cin[i] : 0;
    if (valid) {
        float r = rsqrtf((float)(c + 1));
        d_dis[i] = r;
        d_s1[i]  = r * r * x[i];
    }
    unsigned mask = 0xffffffffu;
    int incl = c;
#pragma unroll
    for (int off = 1; off < 32; off <<= 1) {
        int v = __shfl_up_sync(mask, incl, off);
        if (lane >= off) incl += v;
    }
    int total = __shfl_sync(mask, incl, 31);
    int base = 0;
    if (lane == 31) base = atomicAdd(&d_alloc, total);
    base = __shfl_sync(mask, base, 31);
    if (valid) {
        int start = base + incl - c;
        d_rowptr[i] = start;
        d_cursor[i] = start;
    }
}

// CSR fill + edge contribution to s1, 2 edges/thread (MLP)
__global__ void k_fill(const void* __restrict__ ei, const float* __restrict__ x) {
    int base = (blockIdx.x * blockDim.x + threadIdx.x) * 2;
    int s[2], d[2];
#pragma unroll
    for (int j = 0; j < 2; j++) {
        int e = base + j;
        if (e < N_EDGES) { s[j] = load_idx(ei, e); d[j] = load_idx(ei, N_EDGES + e); }
        else { s[j] = -1; d[j] = 0; }
    }
    float ds[2], dd[2], xs[2];
#pragma unroll
    for (int j = 0; j < 2; j++) {
        if (s[j] >= 0) { ds[j] = d_dis[s[j]]; dd[j] = d_dis[d[j]]; xs[j] = x[s[j]]; }
    }
#pragma unroll
    for (int j = 0; j < 2; j++) {
        if (s[j] < 0) continue;
        float nv = ds[j] * dd[j];
        int pos = atomicAdd(&d_cursor[d[j]], 1);
        d_epay[pos] = make_int2(s[j], __float_as_int(nv));
        atomicAdd(&d_s1[d[j]], nv * xs[j]);
    }
}

// ---------------- layer 1 gather: a2 = fp16(A_hat @ h1), 2-edge pipelined ----------------
__global__ __launch_bounds__(256)
void k_gather1(const float* __restrict__ W1, const float* __restrict__ b1) {
    __shared__ float sW[D1], sB[D1];
    int tid = threadIdx.x;
    if (tid < D1) { sW[tid] = W1[tid]; sB[tid] = b1[tid]; }
    __syncthreads();
    int warp = tid >> 5, lane = tid & 31;
    int node = blockIdx.x * 8 + warp;
    if (node >= N_NODES) return;
    float w[8], b[8];
#pragma unroll
    for (int q = 0; q < 8; q++) { w[q] = sW[lane * 8 + q]; b[q] = sB[lane * 8 + q]; }
    float acc[8];
    float dis = d_dis[node];
    float coef = dis * dis, sv = d_s1[node];
#pragma unroll
    for (int q = 0; q < 8; q++) acc[q] = coef * fmaxf(fmaf(sv, w[q], b[q]), 0.0f);
    int beg = d_rowptr[node], end = beg + d_cin[node];
    int e = beg;
    for (; e + 1 < end; e += 2) {
        int2 p0 = d_epay[e], p1 = d_epay[e + 1];
        float n0 = __int_as_float(p0.y), n1 = __int_as_float(p1.y);
        float s0 = d_s1[p0.x], s1v = d_s1[p1.x];       // independent loads (MLP 2)
#pragma unroll
        for (int q = 0; q < 8; q++) {
            acc[q] = fmaf(n0, fmaxf(fmaf(s0, w[q], b[q]), 0.0f), acc[q]);
            acc[q] = fmaf(n1, fmaxf(fmaf(s1v, w[q], b[q]), 0.0f), acc[q]);
        }
    }
    if (e < end) {
        int2 p0 = d_epay[e];
        float n0 = __int_as_float(p0.y);
        float s0 = d_s1[p0.x];
#pragma unroll
        for (int q = 0; q < 8; q++)
            acc[q] = fmaf(n0, fmaxf(fmaf(s0, w[q], b[q]), 0.0f), acc[q]);
    }
    uint32_t hw[4];
#pragma unroll
    for (int q2 = 0; q2 < 4; q2++) hw[q2] = f2h2(acc[q2 * 2], acc[q2 * 2 + 1]);
    size_t off = (size_t)node * D1 + lane * 8;
    *(uint4*)(d_a2h + off) = make_uint4(hw[0], hw[1], hw[2], hw[3]);
}

// ---------------- layer 2 gather: a3 = fp16(A_hat @ h2), 2-edge pipelined ----------------
__device__ __forceinline__ void acc_hu(float* acc, const uint4& h0, const uint4& h1, float nv) {
    const uint32_t hu[8] = {h0.x, h0.y, h0.z, h0.w, h1.x, h1.y, h1.z, h1.w};
#pragma unroll
    for (int q = 0; q < 8; q++) {
        float2 hv = h2f2(hu[q]);
        acc[q * 2 + 0] = fmaf(nv, hv.x, acc[q * 2 + 0]);
        acc[q * 2 + 1] = fmaf(nv, hv.y, acc[q * 2 + 1]);
    }
}

__global__ __launch_bounds__(256)
void k_gather2(void) {
    int tid = threadIdx.x;
    int warp = tid >> 5, lane = tid & 31;
    int node = blockIdx.x * 8 + warp;
    if (node >= N_NODES) return;
    float acc[16];
#pragma unroll
    for (int q = 0; q < 16; q++) acc[q] = 0.0f;
    float dis = d_dis[node];
    {
        size_t off = (size_t)node * D2 + lane * 16;
        uint4 h0 = *(const uint4*)(d_h2h + off);
        uint4 h1 = *(const uint4*)(d_h2h + off + 8);
        acc_hu(acc, h0, h1, dis * dis);
    }
    int beg = d_rowptr[node], end = beg + d_cin[node];
    int e = beg;
    for (; e + 1 < end; e += 2) {
        int2 p0 = d_epay[e], p1 = d_epay[e + 1];
        size_t o0 = (size_t)p0.x * D2 + lane * 16;
        size_t o1 = (size_t)p1.x * D2 + lane * 16;
        // 4 independent 16B loads in flight before any FMA (MLP 4)
        uint4 a0 = *(const uint4*)(d_h2h + o0);
        uint4 a1 = *(const uint4*)(d_h2h + o0 + 8);
        uint4 b0 = *(const uint4*)(d_h2h + o1);
        uint4 b1 = *(const uint4*)(d_h2h + o1 + 8);
        acc_hu(acc, a0, a1, __int_as_float(p0.y));
        acc_hu(acc, b0, b1, __int_as_float(p1.y));
    }
    if (e < end) {
        int2 p0 = d_epay[e];
        size_t o0 = (size_t)p0.x * D2 + lane * 16;
        uint4 a0 = *(const uint4*)(d_h2h + o0);
        uint4 a1 = *(const uint4*)(d_h2h + o0 + 8);
        acc_hu(acc, a0, a1, __int_as_float(p0.y));
    }
    uint32_t hw[8];
#pragma unroll
    for (int q2 = 0; q2 < 8; q2++) hw[q2] = f2h2(acc[q2 * 2], acc[q2 * 2 + 1]);
    size_t off = (size_t)node * D2 + lane * 16;
    *(uint4*)(d_a3h + off)     = make_uint4(hw[0], hw[1], hw[2], hw[3]);
    *(uint4*)(d_a3h + off + 8) = make_uint4(hw[4], hw[5], hw[6], hw[7]);
}

// W [K, N] fp32 row-major -> B [N, K] fp16 (transposed, K-major), tiled/coalesced
__global__ __launch_bounds__(256)
void k_wconv(const float* __restrict__ W, __half* __restrict__ bh, int K, int N) {
    __shared__ float tile[32][33];
    int n0 = blockIdx.x * 32, k0 = blockIdx.y * 32;
    int tx = threadIdx.x & 31, ty = threadIdx.x >> 5;   // 32 x 8
#pragma unroll
    for (int j = 0; j < 32; j += 8)
        tile[ty + j][tx] = W[(size_t)(k0 + ty + j) * N + n0 + tx];
    __syncthreads();
#pragma unroll
    for (int j = 0; j < 32; j += 8)
        bh[(size_t)(n0 + ty + j) * K + k0 + tx] = __float2half_rn(tile[tx][ty + j]);
}

// ---------------- fp16 GEMM: ldmatrix + 3-stage cp.async pipeline, 1 sync/chunk ----------------
// mode 0: h2 = relu(D+bias) stored as fp16                  (layer 2)
// mode 1: relu(D+bias) pooled into d_pool[batch]            (layer 3)
__global__ __launch_bounds__(256, 2)
void mma_gemm(const __half* __restrict__ A, const __half* __restrict__ B,
              const float* __restrict__ bias, const void* __restrict__ batch,
              int M, int Nglob, int K, int mode) {
    extern __shared__ __align__(16) char dynsm[];

    const int tid = threadIdx.x;
    const int wid = tid >> 5, lane = tid & 31;
    const int g = lane >> 2, tig = lane & 3;
    const int warp_m = wid & 3, warp_n = wid >> 2;
    const int row0 = blockIdx.y * 128, col0 = blockIdx.x * 128;
    const int mr = warp_m * 32, nc = warp_n * 64;

    const int t   = lane >> 3;
    const int thi = t >> 1;
    const int rlo = (t & 1) * 8 + (lane & 7);

    const uint32_t smbase = smem_u32(dynsm);
    const uint32_t stA[3] = { smbase, smbase + 32768u, smbase + 65536u };
    const uint32_t stB[3] = { smbase + 16384u, smbase + 49152u, smbase + 81920u };

    int rA0 = mr + rlo, rA1 = mr + 16 + rlo;
    uint32_t aoff0 = (uint32_t)(rA0 * 128), amask0 = (uint32_t)(rA0 & 7);
    uint32_t aoff1 = (uint32_t)(rA1 * 128), amask1 = (uint32_t)(rA1 & 7);
    uint32_t boff[4], bmask[4];
#pragma unroll
    for (int p = 0; p < 4; p++) {
        int rB = nc + p * 16 + rlo;
        boff[p] = (uint32_t)(rB * 128);
        bmask[p] = (uint32_t)(rB & 7);
    }

    float acc[2][8][4];
#pragma unroll
    for (int mf = 0; mf < 2; mf++)
#pragma unroll
        for (int nf = 0; nf < 8; nf++)
#pragma unroll
            for (int q = 0; q < 4; q++) acc[mf][nf][q] = 0.0f;

    const int nk = K >> 6;

    const int lr = tid >> 1;
    const int lc2 = (tid & 1) * 4;
    auto prefetch = [&](int kc, int s) {
        const int kof = kc << 6;
        int grow = row0 + lr;
        uint32_t asz = (grow < M) ? 16u : 0u;
        const __half* agp = A + (size_t)grow * K + kof + lc2 * 8;
        const __half* bgp = B + (size_t)(col0 + lr) * K + kof + lc2 * 8;
        uint32_t arow = (uint32_t)(lr * 128);
#pragma unroll
        for (int j = 0; j < 4; j++) {
            int ch = lc2 + j;
            uint32_t soff = arow + (uint32_t)(((ch ^ (lr & 7)) << 4));
            cp_async16(stA[s] + soff, agp + j * 8, asz);
            cp_async16(stB[s] + soff, bgp + j * 8, 16u);
        }
        cp_commit();
    };

    prefetch(0, 0);
    if (nk > 1) prefetch(1, 1);
    int sidx = 0;
    for (int kc = 0; kc < nk; kc++) {
        if (kc == nk - 1) {
            asm volatile("cp.async.wait_group 0;" ::: "memory");
        } else {
            asm volatile("cp.async.wait_group 1;" ::: "memory");
        }
        __syncthreads();
        if (kc + 2 < nk) prefetch(kc + 2, (sidx + 2) % 3);
        const int s = sidx;

#pragma unroll
        for (int ks = 0; ks < 4; ks++) {
            const uint32_t kg = (uint32_t)(2 * ks + thi);
            uint32_t a0[4], a1[4];
            ldm_x4(a0, stA[s] + aoff0 + (((kg ^ amask0) << 4)));
            ldm_x4(a1, stA[s] + aoff1 + (((kg ^ amask1) << 4)));
#pragma unroll
            for (int p = 0; p < 4; p++) {
                uint32_t bf[4];
                ldm_x4(bf, stB[s] + boff[p] + (((kg ^ bmask[p]) << 4)));
                mma16816(acc[0][2 * p + 0], a0, bf[0], bf[2]);
                mma16816(acc[0][2 * p + 1], a0, bf[1], bf[3]);
                mma16816(acc[1][2 * p + 0], a1, bf[0], bf[2]);
                mma16816(acc[1][2 * p + 1], a1, bf[1], bf[3]);
            }
        }
        sidx = (sidx + 1) % 3;
    }

    // ---------------- epilogue ----------------
    if (mode == 0) {
#pragma unroll
        for (int mf = 0; mf < 2; mf++) {
#pragma unroll
            for (int half = 0; half < 2; half++) {
                int row = row0 + mr + mf * 16 + g + half * 8;
                if (row >= M) continue;
#pragma unroll
                for (int nf = 0; nf < 8; nf++) {
                    int col = col0 + nc + nf * 8 + tig * 2;
                    float2 bv = *(const float2*)&bias[col];
                    float v0 = fmaxf(acc[mf][nf][half * 2 + 0] + bv.x, 0.0f);
                    float v1 = fmaxf(acc[mf][nf][half * 2 + 1] + bv.y, 0.0f);
                    *(uint32_t*)(d_h2h + (size_t)row * D2 + col) = f2h2(v0, v1);
                }
            }
        }
    } else {
#pragma unroll
        for (int mf = 0; mf < 2; mf++) {
            int ra = row0 + mr + mf * 16 + g;
            int v0ok = (ra < M), v1ok = (ra + 8 < M);
#pragma unroll
            for (int nf = 0; nf < 8; nf++) {
                int col = col0 + nc + nf * 8 + tig * 2;
                float2 bv = *(const float2*)&bias[col];
                acc[mf][nf][0] = v0ok ? fmaxf(acc[mf][nf][0] + bv.x, 0.0f) : 0.0f;
                acc[mf][nf][1] = v0ok ? fmaxf(acc[mf][nf][1] + bv.y, 0.0f) : 0.0f;
                acc[mf][nf][2] = v1ok ? fmaxf(acc[mf][nf][2] + bv.x, 0.0f) : 0.0f;
                acc[mf][nf][3] = v1ok ? fmaxf(acc[mf][nf][3] + bv.y, 0.0f) : 0.0f;
            }
        }
        unsigned mask = 0xffffffffu;
        int rv = row0 + mr + lane;
        int bl = (rv < N_NODES) ? load_idx(batch, rv) : -1;
        int b0 = __shfl_sync(mask, bl, 0);
        bool uni = __all_sync(mask, bl == b0);
        if (uni && b0 >= 0) {
            float s[8][2];
#pragma unroll
            for (int nf = 0; nf < 8; nf++) {
                s[nf][0] = acc[0][nf][0] + acc[0][nf][2] + acc[1][nf][0] + acc[1][nf][2];
                s[nf][1] = acc[0][nf][1] + acc[0][nf][3] + acc[1][nf][1] + acc[1][nf][3];
            }
#pragma unroll
            for (int off = 4; off < 32; off <<= 1)
#pragma unroll
                for (int nf = 0; nf < 8; nf++) {
                    s[nf][0] += __shfl_xor_sync(mask, s[nf][0], off);
                    s[nf][1] += __shfl_xor_sync(mask, s[nf][1], off);
                }
            if (lane < 4) {
#pragma unroll
                for (int nf = 0; nf < 8; nf++) {
                    int col = col0 + nc + nf * 8 + lane * 2;
                    red_add_v2(&d_pool[(size_t)b0 * D3 + col], s[nf][0], s[nf][1]);
                }
            }
        } else {
#pragma unroll
            for (int mf = 0; mf < 2; mf++)
#pragma unroll
                for (int half = 0; half < 2; half++) {
                    int row = row0 + mr + mf * 16 + g + half * 8;
                    if (row >= M) continue;
                    int gb = load_idx(batch, row);
#pragma unroll
                    for (int nf = 0; nf < 8; nf++) {
                        int col = col0 + nc + nf * 8 + tig * 2;
                        red_add_v2(&d_pool[(size_t)gb * D3 + col],
                                   acc[mf][nf][half * 2], acc[mf][nf][half * 2 + 1]);
                    }
                }
        }
    }
}

// ---------------- final linear [16,1024] @ [1024,1024], K-split + atomics ----------------
__global__ void k_final_acc(const float* __restrict__ Wo, float* __restrict__ out) {
    __shared__ __align__(16) float sp[128][NGRAPH];
    __shared__ float sinv[NGRAPH];
    int tid = threadIdx.x;
    int c = blockIdx.x * 256 + tid;
    int k0 = blockIdx.y * 128;
    if (tid < NGRAPH) sinv[tid] = 1.0f / fmaxf(d_cnt[tid], 1.0f);
    for (int i = tid; i < 128 * NGRAPH; i += 256) {
        int k = i >> 4, g = i & 15;
        sp[k][g] = d_pool[(size_t)g * D3 + k0 + k];
    }
    __syncthreads();
    float acc[NGRAPH];
#pragma unroll
    for (int g = 0; g < NGRAPH; g++) acc[g] = 0.0f;
#pragma unroll 4
    for (int k = 0; k < 128; k++) {
        float w = Wo[(size_t)(k0 + k) * D3 + c];
        const float4* pr = (const float4*)sp[k];
#pragma unroll
        for (int q = 0; q < 4; q++) {
            float4 pv = pr[q];
            acc[q * 4 + 0] = fmaf(pv.x, w, acc[q * 4 + 0]);
            acc[q * 4 + 1] = fmaf(pv.y, w, acc[q * 4 + 1]);
            acc[q * 4 + 2] = fmaf(pv.z, w, acc[q * 4 + 2]);
            acc[q * 4 + 3] = fmaf(pv.w, w, acc[q * 4 + 3]);
        }
    }
#pragma unroll
    for (int g = 0; g < NGRAPH; g++)
        red_add_f32(&out[(size_t)g * D3 + c], acc[g] * sinv[g]);
}

// ---------------- launcher ----------------
extern "C" void kernel_launch(void* const* d_in, const int* in_sizes, int n_in,
                              void* d_out, int out_size) {
    const float *x, *W1, *b1, *W2, *b2, *W3, *b3, *Wo, *bo;
    const void *ei, *batch;
    if (in_sizes[0] == N_NODES) {           // dict order
        x     = (const float*)d_in[0];
        ei    = d_in[1];
        batch = d_in[2];
        W1 = (const float*)d_in[3];  b1 = (const float*)d_in[4];
        W2 = (const float*)d_in[5];  b2 = (const float*)d_in[6];
        W3 = (const float*)d_in[7];  b3 = (const float*)d_in[8];
        Wo = (const float*)d_in[9];  bo = (const float*)d_in[10];
    } else {                                // alphabetical order
        W1 = (const float*)d_in[0];
        W2 = (const float*)d_in[1];
        W3 = (const float*)d_in[2];
        Wo = (const float*)d_in[3];
        b1 = (const float*)d_in[4];
        b2 = (const float*)d_in[5];
        b3 = (const float*)d_in[6];
        batch = d_in[7];
        bo = (const float*)d_in[8];
        ei = d_in[9];
        x  = (const float*)d_in[10];
    }
    float* out = (float*)d_out;

    __half *a2h, *a3h, *b2h, *b3h;
    cudaGetSymbolAddress((void**)&a2h, d_a2h);
    cudaGetSymbolAddress((void**)&a3h, d_a3h);
    cudaGetSymbolAddress((void**)&b2h, d_b2h);
    cudaGetSymbolAddress((void**)&b3h, d_b3h);

    static int init_done = 0;
    static cudaStream_t s_side;
    static cudaEvent_t ev_fork, ev_join;
    if (!init_done) {
        cudaFuncSetAttribute(mma_gemm, cudaFuncAttributeMaxDynamicSharedMemorySize, 98304);
        cudaStreamCreateWithFlags(&s_side, cudaStreamNonBlocking);
        cudaEventCreateWithFlags(&ev_fork, cudaEventDisableTiming);
        cudaEventCreateWithFlags(&ev_join, cudaEventDisableTiming);
        init_done = 1;
    }

    const int TB = 256;
    int nb_nodes = (N_NODES + TB - 1) / TB;
    int nb_deg   = (N_EDGES + TB * 8 - 1) / (TB * 8);
    int nb_fill  = (N_EDGES + TB * 2 - 1) / (TB * 2);
    int nb_node8 = (N_NODES + 7) / 8;

    // fork: weight conversions on the side stream, overlapped with graph setup
    cudaEventRecord(ev_fork, 0);
    cudaStreamWaitEvent(s_side, ev_fork, 0);
    {
        dim3 g2w(D2 / 32, D1 / 32);
        k_wconv<<<g2w, 256, 0, s_side>>>(W2, b2h, D1, D2);
        dim3 g3w(D3 / 32, D2 / 32);
        k_wconv<<<g3w, 256, 0, s_side>>>(W3, b3h, D2, D3);
    }
    cudaEventRecord(ev_join, s_side);

    // main chain
    k_init<<<nb_nodes, TB>>>(ei, bo, out);
    k_deg_cnt<<<nb_deg, TB>>>(ei, batch);
    k_dis_s1<<<nb_nodes, TB>>>(x);
    k_fill<<<nb_fill, TB>>>(ei, x);
    k_gather1<<<nb_node8, TB>>>(W1, b1);

    // join weight conversions before first GEMM
    cudaStreamWaitEvent(0, ev_join, 0);

    // layer 2 GEMM: h2 = relu(a2 @ W2 + b2) stored fp16
    {
        dim3 grid(D2 / 128, (N_NODES + 127) / 128);
        mma_gemm<<<grid, 256, 98304>>>(a2h, b2h, b2, nullptr, N_NODES, D2, D1, 0);
    }

    // layer 2 aggregation: gather, emit a3 fp16 directly
    k_gather2<<<nb_node8, TB>>>();

    // layer 3 GEMM with fused pooling
    {
        dim3 grid(D3 / 128, (N_NODES + 127) / 128);
        mma_gemm<<<grid, 256, 98304>>>(a3h, b3h, b3, batch, N_NODES, D3, D2, 1);
    }

    // final linear, K-split across 32 blocks
    {
        dim3 grid(4, 8);
        k_final_acc<<<grid, 256>>>(Wo, out);
    }
}